// round 3
// baseline (speedup 1.0000x reference)
#include <cuda_runtime.h>
#include <cstdint>

// ---------------------------------------------------------------------------
// PreferencePredictor fused kernel (sm_100a)
//
// Math reduction:
//   l      = llm @ Wl.T + bl                     [M,256]
//   scores = llm @ W_s2.T + b_s2                 [M,8]   (q-proj + k-dot folded)
//   a0_h   = sigmoid(s[h,0]-s[h,1])
//   att    = base + sum_h a0_h * c_h             [256]   (v + out_proj folded)
//   logit  = relu(att)@Wo[:256] + relu(l)@Wo[256:] + bo
//
// One big GEMM: [M,768] @ [768,264] in tf32 via mma.sync.m16n8k8
// ---------------------------------------------------------------------------

#define NTILE 33      // 264 / 8
#define KTILES 24     // 768 / 32
#define ASZ (128*36)  // A stage floats (BM=128, BK=32, pad to 36)
#define BSZ (264*36)  // B stage floats
#define EPI_OFF (3*(ASZ+BSZ))
#define SMEM_FLOATS (EPI_OFF + 1792)
#define SMEM_BYTES (SMEM_FLOATS*4)

// ---- persistent scratch (static device globals: allocation-free) ----
// NOTE: __align__(256) is load-bearing — cp.async.cg 16B requires 16B-aligned
// global addresses and bare __device__ float[] only guarantees 4B.
__device__ __align__(256) float g_u[256], g_qv[256];
__device__ __align__(256) float g_k[512], g_v[512];      // [2][256]
__device__ __align__(256) float g_Ws[8*256], g_bs[8];
__device__ __align__(256) float g_base[256], g_cc[4*256];
__device__ __align__(256) float g_W[264*768];            // tf32-rounded combined weights [n][k]
__device__ __align__(256) float g_bcomb[264];

// ---- helpers ----
__device__ __forceinline__ uint32_t f2tf32(float f){
    uint32_t u; asm("cvt.rna.tf32.f32 %0, %1;" : "=r"(u) : "f"(f)); return u;
}
__device__ __forceinline__ void cpa16(uint32_t dst, const void* src){
    asm volatile("cp.async.cg.shared.global [%0], [%1], 16;" :: "r"(dst), "l"(src));
}
__device__ __forceinline__ void cp_commit(){ asm volatile("cp.async.commit_group;" ::: "memory"); }
__device__ __forceinline__ void cp_wait2(){ asm volatile("cp.async.wait_group 2;" ::: "memory"); }

__device__ __forceinline__ void mma_tf32(float&c0,float&c1,float&c2,float&c3,
                                         uint32_t a0,uint32_t a1,uint32_t a2,uint32_t a3,
                                         uint32_t b0,uint32_t b1){
    asm volatile(
        "mma.sync.aligned.m16n8k8.row.col.f32.tf32.tf32.f32 "
        "{%0,%1,%2,%3},{%4,%5,%6,%7},{%8,%9},{%0,%1,%2,%3};"
        : "+f"(c0),"+f"(c1),"+f"(c2),"+f"(c3)
        : "r"(a0),"r"(a1),"r"(a2),"r"(a3),"r"(b0),"r"(b1));
}
__device__ __forceinline__ float wreduce(float s){
    #pragma unroll
    for (int o=16;o;o>>=1) s += __shfl_xor_sync(0xffffffffu, s, o);
    return s;
}

// ---- prep 1: u, qv (512 warp-reduced 768-dots) ----
__global__ void __launch_bounds__(256) prep_uq(
    const float* __restrict__ user, const float* __restrict__ query,
    const float* __restrict__ Wu, const float* __restrict__ bu,
    const float* __restrict__ Wq, const float* __restrict__ bq){
    int w = blockIdx.x*8 + (threadIdx.x>>5);
    int lane = threadIdx.x&31;
    const float *x, *W, *b; float* out; int i;
    if (w < 256){ x=user;  W=Wu; b=bu; out=g_u;  i=w; }
    else        { x=query; W=Wq; b=bq; out=g_qv; i=w-256; }
    float s=0.f;
    #pragma unroll
    for (int t=0;t<24;t++){ int jj=lane+t*32; s += x[jj]*W[i*768+jj]; }
    s = wreduce(s);
    if (!lane) out[i] = s + b[i];
}

// ---- prep 2: k, v (1024 warp-reduced 256-dots) ----
__global__ void __launch_bounds__(256) prep_kv(
    const float* __restrict__ ipw, const float* __restrict__ ipb){
    int w = blockIdx.x*8 + (threadIdx.x>>5);   // 0..1023
    int lane = threadIdx.x&31;
    int i = w & 255;
    int which = w >> 8;          // 0..3
    int c = which & 1;           // 0: u-row, 1: qv-row
    int kv = which >> 1;         // 0: K, 1: V
    const float* ctx = c ? g_qv : g_u;
    int row = 256 + kv*256 + i;  // in_proj row
    float s=0.f;
    #pragma unroll
    for (int t=0;t<8;t++){ int jj=lane+t*32; s += ctx[jj]*ipw[row*256+jj]; }
    s = wreduce(s);
    if (!lane){
        float val = s + ipb[row];
        if (kv) g_v[c*256+i] = val; else g_k[c*256+i] = val;
    }
}

// ---- prep 3: W_s, b_s, base, c (3336 warp tasks) ----
__global__ void __launch_bounds__(256) prep_small(
    const float* __restrict__ ipw, const float* __restrict__ ipb,
    const float* __restrict__ opw, const float* __restrict__ opb){
    int w = blockIdx.x*8 + (threadIdx.x>>5);
    int lane = threadIdx.x&31;
    float s=0.f;
    if (w < 256){                       // base[i] (uses v1)
        int i=w;
        #pragma unroll
        for (int t=0;t<8;t++){ int jj=lane+t*32; s += g_v[256+jj]*opw[i*256+jj]; }
        s = wreduce(s);
        if (!lane) g_base[i] = s + opb[i];
    } else if (w < 1280){               // c[h][i]  (v0-v1 slice h)
        int o=w-256, h=o>>8, i=o&255;
        #pragma unroll
        for (int t=0;t<2;t++){ int d=lane+t*32; int jj=h*64+d;
            s += (g_v[jj]-g_v[256+jj])*opw[i*256+jj]; }
        s = wreduce(s);
        if (!lane) g_cc[h*256+i] = s;
    } else if (w < 3328){               // W_s[r][i]
        int o=w-1280, r=o>>8, i=o&255, h=r>>1, kidx=r&1;
        #pragma unroll
        for (int t=0;t<2;t++){ int d=lane+t*32;
            s += g_k[kidx*256+h*64+d]*ipw[(h*64+d)*256+i]; }
        s = wreduce(s);
        if (!lane) g_Ws[r*256+i] = 0.125f*s;
    } else if (w < 3336){               // b_s[r]
        int r=w-3328, h=r>>1, kidx=r&1;
        #pragma unroll
        for (int t=0;t<2;t++){ int d=lane+t*32;
            s += ipb[h*64+d]*g_k[kidx*256+h*64+d]; }
        s = wreduce(s);
        if (!lane) g_bs[r] = 0.125f*s;
    }
}

// ---- prep 4: combined weight [264,768] (tf32) + combined bias ----
__global__ void __launch_bounds__(256) prep_comb(
    const float* __restrict__ Wl, const float* __restrict__ bl){
    int idx = blockIdx.x*256 + threadIdx.x;   // < 264*768
    int n = idx/768, kk = idx - n*768;
    float val;
    if (n < 256){
        val = Wl[idx];                         // rows 0..255 = Wl
    } else {
        int r = n-256; val = 0.f;              // rows 256..263 = W_s @ Wl
        for (int t=0;t<256;t++) val += g_Ws[r*256+t]*Wl[t*768+kk];
    }
    g_W[idx] = __uint_as_float(f2tf32(val));
    if (idx < 264){
        if (idx < 256) g_bcomb[idx] = bl[idx];
        else {
            int r = idx-256; float s = g_bs[r];
            for (int t=0;t<256;t++) s += g_Ws[r*256+t]*bl[t];
            g_bcomb[idx] = s;
        }
    }
}

// ---- main fused GEMM + epilogue ----
__global__ void __launch_bounds__(256,1) main_gemm(
    const float* __restrict__ llm, const float* __restrict__ Wo,
    const float* __restrict__ bo, float* __restrict__ out){
    extern __shared__ float sm[];
    const int tid = threadIdx.x, lane = tid&31, warp = tid>>5;
    const int j = lane&3, qq = lane>>2;
    const uint32_t smu = (uint32_t)__cvta_generic_to_shared(sm);
    float* epi = sm + EPI_OFF;

    auto issue = [&](int st, int kt){
        const float* Asrc = llm + (size_t)blockIdx.x*(128*768) + kt*32;
        uint32_t abase = smu + (uint32_t)(st*ASZ)*4u;
        #pragma unroll
        for (int ch=tid; ch<1024; ch+=256){
            int row=ch>>3, off=(ch&7)*4;
            cpa16(abase + (uint32_t)(row*36+off)*4u, Asrc + (size_t)row*768 + off);
        }
        const float* Bsrc = g_W + kt*32;
        uint32_t bbase = smu + (uint32_t)(3*ASZ + st*BSZ)*4u;
        for (int ch=tid; ch<2112; ch+=256){
            int row=ch>>3, off=(ch&7)*4;
            cpa16(bbase + (uint32_t)(row*36+off)*4u, Bsrc + row*768 + off);
        }
    };

    issue(0,0); cp_commit();
    issue(1,1); cp_commit();

    // stage epilogue constants into smem (overlaps with async loads)
    {
        int i = tid;                      // 256 threads, one each
        epi[i]        = g_base[i];
        epi[1280+i]   = __ldg(Wo+i);      // Wo_att
        epi[1536+i]   = __ldg(Wo+256+i);  // Wo_l
        #pragma unroll
        for (int t=0;t<4;t++) epi[256 + t*256 + i] = g_cc[t*256 + i];
    }

    // accumulators init = bias (cols n0+2j, n0+2j+1; rows g and g+8 share cols)
    float acc[NTILE][4];
    #pragma unroll
    for (int nt=0; nt<NTILE; nt++){
        float b0v = g_bcomb[nt*8+2*j], b1v = g_bcomb[nt*8+2*j+1];
        acc[nt][0]=b0v; acc[nt][1]=b1v; acc[nt][2]=b0v; acc[nt][3]=b1v;
    }

    int st_c=0, st_i=2;
    const int lr = warp*16 + qq;
    for (int kt=0; kt<KTILES; kt++){
        if (kt+2 < KTILES) issue(st_i, kt+2);
        cp_commit();                       // always commit (keeps group math constant)
        cp_wait2();
        __syncthreads();
        const float* Ab = sm + st_c*ASZ;
        const float* Bb = sm + 3*ASZ + st_c*BSZ;
        #pragma unroll
        for (int s8=0; s8<4; s8++){
            int kc = s8*8 + j;
            uint32_t a0 = f2tf32(Ab[lr*36 + kc]);
            uint32_t a1 = f2tf32(Ab[(lr+8)*36 + kc]);
            uint32_t a2 = f2tf32(Ab[lr*36 + kc + 4]);
            uint32_t a3 = f2tf32(Ab[(lr+8)*36 + kc + 4]);
            const float* bp = Bb + qq*36 + kc;
            #pragma unroll
            for (int nt=0; nt<NTILE; nt++){
                uint32_t b0 = __float_as_uint(bp[nt*288]);
                uint32_t b1 = __float_as_uint(bp[nt*288 + 4]);
                mma_tf32(acc[nt][0],acc[nt][1],acc[nt][2],acc[nt][3],a0,a1,a2,a3,b0,b1);
            }
        }
        __syncthreads();
        st_c = (st_c==2)?0:st_c+1;
        st_i = (st_i==2)?0:st_i+1;
    }

    // ---- epilogue: per-row attention + scoring, all in regs/shuffles ----
    const float bo0 = __ldg(bo);
    const int grow = blockIdx.x*128 + warp*16 + qq;
    const int gb = lane & ~3;
    #pragma unroll
    for (int rs=0; rs<2; rs++){
        // score cols 256+2j, 257+2j  -> head j, kidx 0/1
        float s0 = acc[32][rs*2+0];
        float s1 = acc[32][rs*2+1];
        float aj = 1.f/(1.f + expf(s1 - s0));   // softmax weight for v0
        float ah0 = __shfl_sync(0xffffffffu, aj, gb+0);
        float ah1 = __shfl_sync(0xffffffffu, aj, gb+1);
        float ah2 = __shfl_sync(0xffffffffu, aj, gb+2);
        float ah3 = __shfl_sync(0xffffffffu, aj, gb+3);
        float part = 0.f;
        #pragma unroll
        for (int i=0;i<32;i++){                 // relu(l) . Wo_l over owned cols
            int col = i*8 + 2*j;
            part += fmaxf(acc[i][rs*2+0],0.f)*epi[1536+col];
            part += fmaxf(acc[i][rs*2+1],0.f)*epi[1536+col+1];
        }
        #pragma unroll 8
        for (int d=0; d<64; d++){               // relu(att) . Wo_att over dims [64j,64j+64)
            int dd = j*64 + d;
            float att = epi[dd] + ah0*epi[256+dd] + ah1*epi[512+dd]
                                + ah2*epi[768+dd] + ah3*epi[1024+dd];
            part += fmaxf(att,0.f)*epi[1280+dd];
        }
        part += __shfl_xor_sync(0xffffffffu, part, 1);
        part += __shfl_xor_sync(0xffffffffu, part, 2);
        if (j==0) out[grow + rs*8] = part + bo0;
    }
}

// ---------------------------------------------------------------------------
extern "C" void kernel_launch(void* const* d_in, const int* in_sizes, int n_in,
                              void* d_out, int out_size){
    const float* user  = (const float*)d_in[0];
    const float* query = (const float*)d_in[1];
    const float* llm   = (const float*)d_in[2];
    const float* Wu    = (const float*)d_in[3];
    const float* bu    = (const float*)d_in[4];
    const float* Wq    = (const float*)d_in[5];
    const float* bq    = (const float*)d_in[6];
    const float* Wl    = (const float*)d_in[7];
    const float* bl    = (const float*)d_in[8];
    const float* ipw   = (const float*)d_in[9];
    const float* ipb   = (const float*)d_in[10];
    const float* opw   = (const float*)d_in[11];
    const float* opb   = (const float*)d_in[12];
    const float* Wo    = (const float*)d_in[13];
    const float* bo    = (const float*)d_in[14];
    float* out = (float*)d_out;

    int M = in_sizes[2] / 768;

    cudaFuncSetAttribute(main_gemm, cudaFuncAttributeMaxDynamicSharedMemorySize, SMEM_BYTES);

    prep_uq   <<<64, 256>>>(user, query, Wu, bu, Wq, bq);
    prep_kv   <<<128,256>>>(ipw, ipb);
    prep_small<<<417,256>>>(ipw, ipb, opw, opb);
    prep_comb <<<792,256>>>(Wl, bl);
    main_gemm <<<M/128, 256, SMEM_BYTES>>>(llm, Wo, bo, out);
}

// round 5
// speedup vs baseline: 1.2183x; 1.2183x over previous
#include <cuda_runtime.h>
#include <cstdint>
#include <math.h>

// ---------------------------------------------------------------------------
// PreferencePredictor (sm_100, legacy mma.sync tf32) — round 5
//
//   l      = llm @ Wl.T (+bl in epilogue)     [M,256]  GEMM, BM=128 BN=256
//   s_h    = dWs_h . acc + dbsP_h             -> a_h = sigmoid(s_h)
//   att    = base + sum_h a_h * c_h           [256]
//   logit  = relu(att)@Wo[:256] + relu(l)@Wo[256:] + bo
//
// Warp grid 2(M)x4(N); B pre-permuted+swizzled for LDS.128 fragment loads.
// ---------------------------------------------------------------------------

#define KTILES 24
#define ASTRIDE 36
#define A_FLOATS (128*ASTRIDE)            // 4608
#define B_FLOATS (32*256)                 // 8192
#define STAGE_FLOATS (A_FLOATS + B_FLOATS) // 12800
#define NSTAGE 3
#define EPI_F (NSTAGE*STAGE_FLOATS)       // 38400

#define EPI_BASE 0
#define EPI_CC   256
#define EPI_WOA  1280
#define EPI_WOL  1536
#define EPI_BL   1792
#define EPI_DWS  2048
#define EPI_DBS  3072
#define EPI_RED  3080                      // [128][4][5] = 2560
#define EPI_AW   5640                      // [128][4]
#define EPI_PL   6152                      // [128]
#define EPI_RED2 6280                      // [128][2]
#define EPI_TOT  6536
#define SMEM_BYTES ((EPI_F + EPI_TOT)*4)

// ---- persistent scratch ----
__device__ __align__(256) float g_u[256], g_qv[256];
__device__ __align__(256) float g_k[512], g_v[512];
__device__ __align__(256) float g_Ws[8*256], g_bs[8];
__device__ __align__(256) float g_base[256], g_cc[4*256];
__device__ __align__(256) float g_dWs[4*256], g_dbsP[4];
__device__ __align__(256) float g_Wp[256*768];   // permuted tf32 Wl: [kt][kk][qq][nt]

// ---- helpers ----
__device__ __forceinline__ uint32_t f2tf32(float f){
    uint32_t u; asm("cvt.rna.tf32.f32 %0, %1;" : "=r"(u) : "f"(f)); return u;
}
__device__ __forceinline__ void cpa16(uint32_t dst, const void* src){
    asm volatile("cp.async.cg.shared.global [%0], [%1], 16;" :: "r"(dst), "l"(src));
}
__device__ __forceinline__ void cp_commit(){ asm volatile("cp.async.commit_group;" ::: "memory"); }
__device__ __forceinline__ void cp_wait2(){ asm volatile("cp.async.wait_group 2;" ::: "memory"); }

__device__ __forceinline__ void mma_tf32(float&c0,float&c1,float&c2,float&c3,
                                         uint32_t a0,uint32_t a1,uint32_t a2,uint32_t a3,
                                         uint32_t b0,uint32_t b1){
    asm volatile(
        "mma.sync.aligned.m16n8k8.row.col.f32.tf32.tf32.f32 "
        "{%0,%1,%2,%3},{%4,%5,%6,%7},{%8,%9},{%0,%1,%2,%3};"
        : "+f"(c0),"+f"(c1),"+f"(c2),"+f"(c3)
        : "r"(a0),"r"(a1),"r"(a2),"r"(a3),"r"(b0),"r"(b1));
}
__device__ __forceinline__ float wreduce(float s){
    #pragma unroll
    for (int o=16;o;o>>=1) s += __shfl_xor_sync(0xffffffffu, s, o);
    return s;
}

// ---- prep 1: u, qv ----
__global__ void __launch_bounds__(256) prep_uq(
    const float* __restrict__ user, const float* __restrict__ query,
    const float* __restrict__ Wu, const float* __restrict__ bu,
    const float* __restrict__ Wq, const float* __restrict__ bq){
    int w = blockIdx.x*8 + (threadIdx.x>>5);
    int lane = threadIdx.x&31;
    const float *x, *W, *b; float* out; int i;
    if (w < 256){ x=user;  W=Wu; b=bu; out=g_u;  i=w; }
    else        { x=query; W=Wq; b=bq; out=g_qv; i=w-256; }
    float s=0.f;
    #pragma unroll
    for (int t=0;t<24;t++){ int jj=lane+t*32; s += x[jj]*W[i*768+jj]; }
    s = wreduce(s);
    if (!lane) out[i] = s + b[i];
}

// ---- prep 2: k, v ----
__global__ void __launch_bounds__(256) prep_kv(
    const float* __restrict__ ipw, const float* __restrict__ ipb){
    int w = blockIdx.x*8 + (threadIdx.x>>5);   // 0..1023
    int lane = threadIdx.x&31;
    int i = w & 255;
    int which = w >> 8;
    int c = which & 1;
    int kv = which >> 1;
    const float* ctx = c ? g_qv : g_u;
    int row = 256 + kv*256 + i;
    float s=0.f;
    #pragma unroll
    for (int t=0;t<8;t++){ int jj=lane+t*32; s += ctx[jj]*ipw[row*256+jj]; }
    s = wreduce(s);
    if (!lane){
        float val = s + ipb[row];
        if (kv) g_v[c*256+i] = val; else g_k[c*256+i] = val;
    }
}

// ---- prep 3: W_s, b_s, base, c ----
__global__ void __launch_bounds__(256) prep_small(
    const float* __restrict__ ipw, const float* __restrict__ ipb,
    const float* __restrict__ opw, const float* __restrict__ opb){
    int w = blockIdx.x*8 + (threadIdx.x>>5);
    int lane = threadIdx.x&31;
    float s=0.f;
    if (w < 256){
        int i=w;
        #pragma unroll
        for (int t=0;t<8;t++){ int jj=lane+t*32; s += g_v[256+jj]*opw[i*256+jj]; }
        s = wreduce(s);
        if (!lane) g_base[i] = s + opb[i];
    } else if (w < 1280){
        int o=w-256, h=o>>8, i=o&255;
        #pragma unroll
        for (int t=0;t<2;t++){ int d=lane+t*32; int jj=h*64+d;
            s += (g_v[jj]-g_v[256+jj])*opw[i*256+jj]; }
        s = wreduce(s);
        if (!lane) g_cc[h*256+i] = s;
    } else if (w < 3328){
        int o=w-1280, r=o>>8, i=o&255, h=r>>1, kidx=r&1;
        #pragma unroll
        for (int t=0;t<2;t++){ int d=lane+t*32;
            s += g_k[kidx*256+h*64+d]*ipw[(h*64+d)*256+i]; }
        s = wreduce(s);
        if (!lane) g_Ws[r*256+i] = 0.125f*s;
    } else if (w < 3336){
        int r=w-3328, h=r>>1, kidx=r&1;
        #pragma unroll
        for (int t=0;t<2;t++){ int d=lane+t*32;
            s += ipb[h*64+d]*g_k[kidx*256+h*64+d]; }
        s = wreduce(s);
        if (!lane) g_bs[r] = 0.125f*s;
    }
}

// ---- prep 4: dWs, dbsP ----
__global__ void __launch_bounds__(256) prep_const(const float* __restrict__ bl){
    __shared__ float sbuf[4][256];
    int i = threadIdx.x;
    float blv = bl[i];
    #pragma unroll
    for (int h=0;h<4;h++){
        float d = g_Ws[(2*h)*256+i] - g_Ws[(2*h+1)*256+i];
        g_dWs[h*256+i] = d;
        sbuf[h][i] = d * blv;
    }
    __syncthreads();
    if (i < 4){
        float s = g_bs[2*i] - g_bs[2*i+1];
        for (int t=0;t<256;t++) s += sbuf[i][t];
        g_dbsP[i] = s;
    }
}

// ---- prep 5: permuted tf32 weights  g_Wp[kt][kk][qq][nt] = Wl[8nt+qq][32kt+kk]
__global__ void __launch_bounds__(256) prep_Bp(const float* __restrict__ Wl){
    __shared__ float T[32*256];
    int kt = blockIdx.x;          // 0..23
    int n  = threadIdx.x;         // 0..255
    int p  = (n&7)*32 + (n>>3);   // qq*32 + nt
    #pragma unroll
    for (int c=0;c<32;c++) T[c*256 + p] = Wl[n*768 + kt*32 + c];
    __syncthreads();
    float* dst = g_Wp + kt*8192;
    #pragma unroll
    for (int i=0;i<32;i++){
        int o = i*256 + n;        // coalesced
        dst[o] = __uint_as_float(f2tf32(T[o]));
    }
}

// ---- main GEMM + fused epilogue ----
__global__ void __launch_bounds__(256,1) main_gemm(
    const float* __restrict__ llm, const float* __restrict__ Wo,
    const float* __restrict__ bo, const float* __restrict__ bl,
    float* __restrict__ out){
    extern __shared__ float sm[];
    const int tid = threadIdx.x, lane = tid&31, warp = tid>>5;
    const int j = lane&3, qq = lane>>2;
    const int wm = warp&1, wn = warp>>1;           // 2 x 4 warp grid
    const uint32_t smu = (uint32_t)__cvta_generic_to_shared(sm);
    float* epi = sm + EPI_F;

    auto issue = [&](int kt){
        int slot = kt % NSTAGE;
        uint32_t sb = smu + (uint32_t)(slot*STAGE_FLOATS)*4u;
        const float* Asrc = llm + (size_t)blockIdx.x*(128*768) + kt*32;
        #pragma unroll
        for (int ch=tid; ch<1024; ch+=256){
            int row = ch>>3, u = ch&7;
            cpa16(sb + (uint32_t)(row*ASTRIDE + u*4)*4u, Asrc + (size_t)row*768 + u*4);
        }
        const float* Bsrc = g_Wp + kt*8192;
        uint32_t bb = sb + (uint32_t)A_FLOATS*4u;
        #pragma unroll
        for (int ch=tid; ch<2048; ch+=256){
            int r = ch>>3, nt4 = ch&7;
            int grp = ((r>>3)&3)*2 + (r&1);
            cpa16(bb + (uint32_t)(r*32 + ((nt4^grp)<<2))*4u, Bsrc + ch*4);
        }
    };

    issue(0); cp_commit();
    issue(1); cp_commit();

    // stage epilogue constants (overlaps async loads)
    {
        int i = tid;
        epi[EPI_BASE+i] = g_base[i];
        #pragma unroll
        for (int h=0;h<4;h++) epi[EPI_CC + h*256 + i] = g_cc[h*256+i];
        epi[EPI_WOA+i] = __ldg(Wo+i);
        epi[EPI_WOL+i] = __ldg(Wo+256+i);
        epi[EPI_BL +i] = __ldg(bl+i);
        #pragma unroll
        for (int h=0;h<4;h++) epi[EPI_DWS + h*256 + i] = g_dWs[h*256+i];
        if (i<4) epi[EPI_DBS+i] = g_dbsP[i];
    }

    float acc[4][8][4];
    #pragma unroll
    for (int t=0;t<4;t++)
        #pragma unroll
        for (int nt=0;nt<8;nt++)
            #pragma unroll
            for (int c=0;c<4;c++) acc[t][nt][c]=0.f;

    const int grp = j*2 + (qq&1);      // B swizzle group (constant across s8/b0/b1)

    for (int kt=0; kt<KTILES; kt++){
        if (kt+2 < KTILES) issue(kt+2);
        cp_commit();
        cp_wait2();
        __syncthreads();

        const int slot = kt % NSTAGE;
        const float* As = sm + slot*STAGE_FLOATS;
        const float4* Bs4 = (const float4*)(As + A_FLOATS);

        #pragma unroll
        for (int s8=0; s8<4; s8++){
            const int kc = s8*8 + j;
            // B fragments: 4 x LDS.128 (each float4 = 4 n-tiles)
            const int r0 = kc*8 + qq;
            const int r1 = r0 + 32;                 // k + 4
            float4 B0a = Bs4[r0*8 + ((wn*2+0)^grp)];
            float4 B0b = Bs4[r0*8 + ((wn*2+1)^grp)];
            float4 B1a = Bs4[r1*8 + ((wn*2+0)^grp)];
            float4 B1b = Bs4[r1*8 + ((wn*2+1)^grp)];
            const float b0arr[8] = {B0a.x,B0a.y,B0a.z,B0a.w,B0b.x,B0b.y,B0b.z,B0b.w};
            const float b1arr[8] = {B1a.x,B1a.y,B1a.z,B1a.w,B1b.x,B1b.y,B1b.z,B1b.w};
            // A fragments (cvt to tf32 in regs)
            uint32_t a0[4],a1[4],a2[4],a3[4];
            #pragma unroll
            for (int t=0;t<4;t++){
                int row = wm*64 + t*16 + qq;
                a0[t] = f2tf32(As[row*ASTRIDE + kc]);
                a1[t] = f2tf32(As[(row+8)*ASTRIDE + kc]);
                a2[t] = f2tf32(As[row*ASTRIDE + kc + 4]);
                a3[t] = f2tf32(As[(row+8)*ASTRIDE + kc + 4]);
            }
            #pragma unroll
            for (int t=0;t<4;t++)
                #pragma unroll
                for (int nt=0;nt<8;nt++)
                    mma_tf32(acc[t][nt][0],acc[t][nt][1],acc[t][nt][2],acc[t][nt][3],
                             a0[t],a1[t],a2[t],a3[t],
                             __float_as_uint(b0arr[nt]), __float_as_uint(b1arr[nt]));
        }
        __syncthreads();
    }

    // ---- epilogue phase A: per-thread partials over owned cols ----
    float pl[4][2];
    float sh[4][2][4];
    #pragma unroll
    for (int t=0;t<4;t++)
        #pragma unroll
        for (int hf=0;hf<2;hf++){
            pl[t][hf]=0.f;
            #pragma unroll
            for (int h=0;h<4;h++) sh[t][hf][h]=0.f;
        }
    #pragma unroll
    for (int nt=0;nt<8;nt++){
        #pragma unroll
        for (int cb=0;cb<2;cb++){
            const int col = wn*64 + nt*8 + 2*j + cb;
            const float blv = epi[EPI_BL+col];
            const float wol = epi[EPI_WOL+col];
            const float w0 = epi[EPI_DWS+col];
            const float w1 = epi[EPI_DWS+256+col];
            const float w2 = epi[EPI_DWS+512+col];
            const float w3 = epi[EPI_DWS+768+col];
            #pragma unroll
            for (int t=0;t<4;t++)
                #pragma unroll
                for (int hf=0;hf<2;hf++){
                    float av = acc[t][nt][hf*2+cb];
                    pl[t][hf] += fmaxf(av+blv,0.f)*wol;
                    sh[t][hf][0] += w0*av;
                    sh[t][hf][1] += w1*av;
                    sh[t][hf][2] += w2*av;
                    sh[t][hf][3] += w3*av;
                }
        }
    }
    #pragma unroll
    for (int t=0;t<4;t++)
        #pragma unroll
        for (int hf=0;hf<2;hf++){
            float v4 = pl[t][hf];
            v4 += __shfl_xor_sync(0xffffffffu, v4, 1);
            v4 += __shfl_xor_sync(0xffffffffu, v4, 2);
            float vh[4];
            #pragma unroll
            for (int h=0;h<4;h++){
                float v = sh[t][hf][h];
                v += __shfl_xor_sync(0xffffffffu, v, 1);
                v += __shfl_xor_sync(0xffffffffu, v, 2);
                vh[h]=v;
            }
            if (j==0){
                int row = wm*64 + t*16 + qq + hf*8;
                float* rp = epi + EPI_RED + (row*4+wn)*5;
                rp[0]=vh[0]; rp[1]=vh[1]; rp[2]=vh[2]; rp[3]=vh[3]; rp[4]=v4;
            }
        }
    __syncthreads();

    // ---- phase B: per-row scores + sigmoid ----
    if (tid < 128){
        int row = tid;
        float s0=epi[EPI_DBS+0], s1=epi[EPI_DBS+1], s2=epi[EPI_DBS+2], s3=epi[EPI_DBS+3];
        float p=0.f;
        #pragma unroll
        for (int w=0;w<4;w++){
            float* rp = epi + EPI_RED + (row*4+w)*5;
            s0+=rp[0]; s1+=rp[1]; s2+=rp[2]; s3+=rp[3]; p+=rp[4];
        }
        epi[EPI_AW+row*4+0] = 1.f/(1.f+expf(-s0));
        epi[EPI_AW+row*4+1] = 1.f/(1.f+expf(-s1));
        epi[EPI_AW+row*4+2] = 1.f/(1.f+expf(-s2));
        epi[EPI_AW+row*4+3] = 1.f/(1.f+expf(-s3));
        epi[EPI_PL+row] = p;
    }
    __syncthreads();

    // ---- phase C: attention dot, 2 threads per row ----
    {
        int row = tid & 127, hf = tid >> 7;
        float a0=epi[EPI_AW+row*4+0], a1=epi[EPI_AW+row*4+1],
              a2=epi[EPI_AW+row*4+2], a3=epi[EPI_AW+row*4+3];
        float p2=0.f;
        #pragma unroll 8
        for (int d=hf*128; d<hf*128+128; d++){
            float att = epi[EPI_BASE+d] + a0*epi[EPI_CC+d] + a1*epi[EPI_CC+256+d]
                      + a2*epi[EPI_CC+512+d] + a3*epi[EPI_CC+768+d];
            p2 += fmaxf(att,0.f)*epi[EPI_WOA+d];
        }
        epi[EPI_RED2 + row*2 + hf] = p2;
    }
    __syncthreads();

    if (tid < 128){
        out[blockIdx.x*128 + tid] = epi[EPI_PL+tid] + epi[EPI_RED2+tid*2]
                                  + epi[EPI_RED2+tid*2+1] + __ldg(bo);
    }
}

// ---------------------------------------------------------------------------
extern "C" void kernel_launch(void* const* d_in, const int* in_sizes, int n_in,
                              void* d_out, int out_size){
    const float* user  = (const float*)d_in[0];
    const float* query = (const float*)d_in[1];
    const float* llm   = (const float*)d_in[2];
    const float* Wu    = (const float*)d_in[3];
    const float* bu    = (const float*)d_in[4];
    const float* Wq    = (const float*)d_in[5];
    const float* bq    = (const float*)d_in[6];
    const float* Wl    = (const float*)d_in[7];
    const float* bl    = (const float*)d_in[8];
    const float* ipw   = (const float*)d_in[9];
    const float* ipb   = (const float*)d_in[10];
    const float* opw   = (const float*)d_in[11];
    const float* opb   = (const float*)d_in[12];
    const float* Wo    = (const float*)d_in[13];
    const float* bo    = (const float*)d_in[14];
    float* out = (float*)d_out;

    int M = in_sizes[2] / 768;

    cudaFuncSetAttribute(main_gemm, cudaFuncAttributeMaxDynamicSharedMemorySize, SMEM_BYTES);

    prep_uq   <<<64, 256>>>(user, query, Wu, bu, Wq, bq);
    prep_kv   <<<128,256>>>(ipw, ipb);
    prep_small<<<417,256>>>(ipw, ipb, opw, opb);
    prep_const<<<1,  256>>>(bl);
    prep_Bp   <<<24, 256>>>(Wl);
    main_gemm <<<M/128, 256, SMEM_BYTES>>>(llm, Wo, bo, bl, out);
}

// round 7
// speedup vs baseline: 1.9409x; 1.5932x over previous
#include <cuda_runtime.h>
#include <cstdint>
#include <math.h>

// ---------------------------------------------------------------------------
// PreferencePredictor (sm_100, mma.sync m16n8k16 fp16) — round 7 (resubmit of R6;
// R6 bench was an infra failure, kernel never ran)
//
//   l      = llm @ Wl.T (+bl in epilogue)     [M,256]  GEMM, BM=128 BN=256
//   s_h    = dWs_h . acc + dbsP_h             -> a_h = sigmoid(s_h)
//   att    = base + sum_h a_h * c_h           [256]
//   logit  = relu(att)@Wo[:256] + relu(l)@Wo[256:] + bo
//
// fp16 inputs (same 2^-11 roundoff as tf32), fp32 accum. 2x MACs/instr.
// ---------------------------------------------------------------------------

#define KTILES 24
#define ASTRIDE 40                          // floats per A row (conflict-free LDS.64)
#define A_FLOATS (128*ASTRIDE)              // 5120
#define B_U32    4096                       // 16 kpairs x 256 n half2
#define STAGE_FLOATS (A_FLOATS + B_U32)     // 9216 (B stored as u32=half2)
#define NSTAGE 3
#define EPI_F (NSTAGE*STAGE_FLOATS)         // 27648

#define EPI_BASE 0
#define EPI_CC   256
#define EPI_WOA  1280
#define EPI_WOL  1536
#define EPI_BL   1792
#define EPI_DWS  2048
#define EPI_DBS  3072
#define EPI_RED  3080                        // [128][4][5]
#define EPI_AW   5640                        // [128][4]
#define EPI_PL   6152                        // [128]
#define EPI_RED2 6280                        // [128][2]
#define EPI_TOT  6536
#define SMEM_BYTES ((EPI_F + EPI_TOT)*4)

// ---- persistent scratch ----
__device__ __align__(256) float g_u[256], g_qv[256];
__device__ __align__(256) float g_k[512], g_v[512];
__device__ __align__(256) float g_Ws[8*256], g_bs[8];
__device__ __align__(256) float g_base[256], g_cc[4*256];
__device__ __align__(256) float g_dWs[4*256], g_dbsP[4];
__device__ __align__(256) uint32_t g_Wh[24*B_U32];  // half2-packed swizzled Wl

// ---- helpers ----
__device__ __forceinline__ uint32_t packh2(float lo, float hi){
    uint32_t r; asm("cvt.rn.f16x2.f32 %0, %1, %2;" : "=r"(r) : "f"(hi), "f"(lo)); return r;
}
__device__ __forceinline__ void cpa16(uint32_t dst, const void* src){
    asm volatile("cp.async.cg.shared.global [%0], [%1], 16;" :: "r"(dst), "l"(src));
}
__device__ __forceinline__ void cp_commit(){ asm volatile("cp.async.commit_group;" ::: "memory"); }
__device__ __forceinline__ void cp_wait2(){ asm volatile("cp.async.wait_group 2;" ::: "memory"); }

__device__ __forceinline__ void mma_f16(float&c0,float&c1,float&c2,float&c3,
                                        uint32_t a0,uint32_t a1,uint32_t a2,uint32_t a3,
                                        uint32_t b0,uint32_t b1){
    asm volatile(
        "mma.sync.aligned.m16n8k16.row.col.f32.f16.f16.f32 "
        "{%0,%1,%2,%3},{%4,%5,%6,%7},{%8,%9},{%0,%1,%2,%3};"
        : "+f"(c0),"+f"(c1),"+f"(c2),"+f"(c3)
        : "r"(a0),"r"(a1),"r"(a2),"r"(a3),"r"(b0),"r"(b1));
}
__device__ __forceinline__ float wreduce(float s){
    #pragma unroll
    for (int o=16;o;o>>=1) s += __shfl_xor_sync(0xffffffffu, s, o);
    return s;
}

// ---- prep 1: u, qv ----
__global__ void __launch_bounds__(256) prep_uq(
    const float* __restrict__ user, const float* __restrict__ query,
    const float* __restrict__ Wu, const float* __restrict__ bu,
    const float* __restrict__ Wq, const float* __restrict__ bq){
    int w = blockIdx.x*8 + (threadIdx.x>>5);
    int lane = threadIdx.x&31;
    const float *x, *W, *b; float* out; int i;
    if (w < 256){ x=user;  W=Wu; b=bu; out=g_u;  i=w; }
    else        { x=query; W=Wq; b=bq; out=g_qv; i=w-256; }
    float s=0.f;
    #pragma unroll
    for (int t=0;t<24;t++){ int jj=lane+t*32; s += x[jj]*W[i*768+jj]; }
    s = wreduce(s);
    if (!lane) out[i] = s + b[i];
}

// ---- prep 2: k, v ----
__global__ void __launch_bounds__(256) prep_kv(
    const float* __restrict__ ipw, const float* __restrict__ ipb){
    int w = blockIdx.x*8 + (threadIdx.x>>5);   // 0..1023
    int lane = threadIdx.x&31;
    int i = w & 255;
    int which = w >> 8;
    int c = which & 1;
    int kv = which >> 1;
    const float* ctx = c ? g_qv : g_u;
    int row = 256 + kv*256 + i;
    float s=0.f;
    #pragma unroll
    for (int t=0;t<8;t++){ int jj=lane+t*32; s += ctx[jj]*ipw[row*256+jj]; }
    s = wreduce(s);
    if (!lane){
        float val = s + ipb[row];
        if (kv) g_v[c*256+i] = val; else g_k[c*256+i] = val;
    }
}

// ---- prep 3: W_s, b_s, base, c ----
__global__ void __launch_bounds__(256) prep_small(
    const float* __restrict__ ipw, const float* __restrict__ ipb,
    const float* __restrict__ opw, const float* __restrict__ opb){
    int w = blockIdx.x*8 + (threadIdx.x>>5);
    int lane = threadIdx.x&31;
    float s=0.f;
    if (w < 256){
        int i=w;
        #pragma unroll
        for (int t=0;t<8;t++){ int jj=lane+t*32; s += g_v[256+jj]*opw[i*256+jj]; }
        s = wreduce(s);
        if (!lane) g_base[i] = s + opb[i];
    } else if (w < 1280){
        int o=w-256, h=o>>8, i=o&255;
        #pragma unroll
        for (int t=0;t<2;t++){ int d=lane+t*32; int jj=h*64+d;
            s += (g_v[jj]-g_v[256+jj])*opw[i*256+jj]; }
        s = wreduce(s);
        if (!lane) g_cc[h*256+i] = s;
    } else if (w < 3328){
        int o=w-1280, r=o>>8, i=o&255, h=r>>1, kidx=r&1;
        #pragma unroll
        for (int t=0;t<2;t++){ int d=lane+t*32;
            s += g_k[kidx*256+h*64+d]*ipw[(h*64+d)*256+i]; }
        s = wreduce(s);
        if (!lane) g_Ws[r*256+i] = 0.125f*s;
    } else if (w < 3336){
        int r=w-3328, h=r>>1, kidx=r&1;
        #pragma unroll
        for (int t=0;t<2;t++){ int d=lane+t*32;
            s += ipb[h*64+d]*g_k[kidx*256+h*64+d]; }
        s = wreduce(s);
        if (!lane) g_bs[r] = 0.125f*s;
    }
}

// ---- prep 4: dWs, dbsP ----
__global__ void __launch_bounds__(256) prep_const(const float* __restrict__ bl){
    __shared__ float sbuf[4][256];
    int i = threadIdx.x;
    float blv = bl[i];
    #pragma unroll
    for (int h=0;h<4;h++){
        float d = g_Ws[(2*h)*256+i] - g_Ws[(2*h+1)*256+i];
        g_dWs[h*256+i] = d;
        sbuf[h][i] = d * blv;
    }
    __syncthreads();
    if (i < 4){
        float s = g_bs[2*i] - g_bs[2*i+1];
        for (int t=0;t<256;t++) s += sbuf[i][t];
        g_dbsP[i] = s;
    }
}

// ---- prep 5: fp16-packed, fragment-swizzled weights ----
// g_Wh[kt]: cell(kp,qq) = 128B (32 half2 over ntg), chunk swizzle s=(qq&1)*4+(kp&3)
__global__ void __launch_bounds__(256) prep_Bh(const float* __restrict__ Wl){
    int kt = blockIdx.x;          // 0..23
    int n  = threadIdx.x;         // 0..255
    int qq = n & 7, ntg = n >> 3;
    uint32_t* dst = g_Wh + kt*B_U32;
    #pragma unroll
    for (int kp=0; kp<16; kp++){
        float lo = Wl[n*768 + kt*32 + kp*2];
        float hi = Wl[n*768 + kt*32 + kp*2 + 1];
        int s = (qq&1)*4 + (kp&3);
        int chunk = (ntg>>2) ^ s;
        dst[(kp*8+qq)*32 + chunk*4 + (ntg&3)] = packh2(lo, hi);
    }
}

// ---- main GEMM + fused epilogue ----
__global__ void __launch_bounds__(256,1) main_gemm(
    const float* __restrict__ llm, const float* __restrict__ Wo,
    const float* __restrict__ bo, const float* __restrict__ bl,
    float* __restrict__ out){
    extern __shared__ float sm[];
    const int tid = threadIdx.x, lane = tid&31, warp = tid>>5;
    const int j = lane&3, qq = lane>>2;
    const int wm = warp&1, wn = warp>>1;           // 2 x 4 warp grid
    const uint32_t smu = (uint32_t)__cvta_generic_to_shared(sm);
    float* epi = sm + EPI_F;

    auto issue = [&](int kt){
        int slot = kt % NSTAGE;
        uint32_t sb = smu + (uint32_t)(slot*STAGE_FLOATS)*4u;
        const float* Asrc = llm + (size_t)blockIdx.x*(128*768) + kt*32;
        #pragma unroll
        for (int ch=tid; ch<1024; ch+=256){
            int row = ch>>3, u = ch&7;
            cpa16(sb + (uint32_t)(row*ASTRIDE + u*4)*4u, Asrc + (size_t)row*768 + u*4);
        }
        const uint32_t* Bsrc = g_Wh + kt*B_U32;
        uint32_t bb = sb + (uint32_t)A_FLOATS*4u;
        #pragma unroll
        for (int ch=tid; ch<1024; ch+=256)
            cpa16(bb + (uint32_t)ch*16u, Bsrc + ch*4);
    };

    issue(0); cp_commit();
    issue(1); cp_commit();

    // stage epilogue constants (overlaps async loads)
    {
        int i = tid;
        epi[EPI_BASE+i] = g_base[i];
        #pragma unroll
        for (int h=0;h<4;h++) epi[EPI_CC + h*256 + i] = g_cc[h*256+i];
        epi[EPI_WOA+i] = __ldg(Wo+i);
        epi[EPI_WOL+i] = __ldg(Wo+256+i);
        epi[EPI_BL +i] = __ldg(bl+i);
        #pragma unroll
        for (int h=0;h<4;h++) epi[EPI_DWS + h*256 + i] = g_dWs[h*256+i];
        if (i<4) epi[EPI_DBS+i] = g_dbsP[i];
    }

    float acc[4][8][4];
    #pragma unroll
    for (int t=0;t<4;t++)
        #pragma unroll
        for (int nt=0;nt<8;nt++)
            #pragma unroll
            for (int c=0;c<4;c++) acc[t][nt][c]=0.f;

    const int bsw = (qq&1)*4 + j;          // B chunk swizzle key

    for (int kt=0; kt<KTILES; kt++){
        if (kt+2 < KTILES) issue(kt+2);
        cp_commit();
        cp_wait2();
        __syncthreads();

        const int slot = kt % NSTAGE;
        const float* As = sm + slot*STAGE_FLOATS;
        const uint32_t* Bs = (const uint32_t*)(As + A_FLOATS);

        #pragma unroll
        for (int ks=0; ks<2; ks++){
            // B fragments: 4 x LDS.128
            uint32_t bf[2][8];
            #pragma unroll
            for (int r=0;r<2;r++){
                const int kp = ks*8 + j + r*4;
                const uint32_t* cell = Bs + (kp*8+qq)*32;
                #pragma unroll
                for (int c=0;c<2;c++){
                    const int chunk = (wn*2 + c) ^ bsw;
                    const uint4 v = *(const uint4*)(cell + chunk*4);
                    bf[r][c*4+0]=v.x; bf[r][c*4+1]=v.y; bf[r][c*4+2]=v.z; bf[r][c*4+3]=v.w;
                }
            }
            // A fragments: 16 x LDS.64 + cvt
            uint32_t af[4][4];
            const int k0 = ks*16 + 2*j;
            #pragma unroll
            for (int t=0;t<4;t++){
                const int row = wm*64 + t*16 + qq;
                float2 p0 = *(const float2*)(As + row*ASTRIDE + k0);
                float2 p1 = *(const float2*)(As + (row+8)*ASTRIDE + k0);
                float2 p2 = *(const float2*)(As + row*ASTRIDE + k0 + 8);
                float2 p3 = *(const float2*)(As + (row+8)*ASTRIDE + k0 + 8);
                af[t][0] = packh2(p0.x, p0.y);
                af[t][1] = packh2(p1.x, p1.y);
                af[t][2] = packh2(p2.x, p2.y);
                af[t][3] = packh2(p3.x, p3.y);
            }
            #pragma unroll
            for (int t=0;t<4;t++)
                #pragma unroll
                for (int nt=0;nt<8;nt++)
                    mma_f16(acc[t][nt][0],acc[t][nt][1],acc[t][nt][2],acc[t][nt][3],
                            af[t][0],af[t][1],af[t][2],af[t][3],
                            bf[0][nt], bf[1][nt]);
        }
        __syncthreads();
    }

    // ---- epilogue phase A: per-thread partials over owned cols ----
    float pl[4][2];
    float sh[4][2][4];
    #pragma unroll
    for (int t=0;t<4;t++)
        #pragma unroll
        for (int hf=0;hf<2;hf++){
            pl[t][hf]=0.f;
            #pragma unroll
            for (int h=0;h<4;h++) sh[t][hf][h]=0.f;
        }
    #pragma unroll
    for (int nt=0;nt<8;nt++){
        #pragma unroll
        for (int cb=0;cb<2;cb++){
            const int col = wn*64 + nt*8 + 2*j + cb;
            const float blv = epi[EPI_BL+col];
            const float wol = epi[EPI_WOL+col];
            const float w0 = epi[EPI_DWS+col];
            const float w1 = epi[EPI_DWS+256+col];
            const float w2 = epi[EPI_DWS+512+col];
            const float w3 = epi[EPI_DWS+768+col];
            #pragma unroll
            for (int t=0;t<4;t++)
                #pragma unroll
                for (int hf=0;hf<2;hf++){
                    float av = acc[t][nt][hf*2+cb];
                    pl[t][hf] += fmaxf(av+blv,0.f)*wol;
                    sh[t][hf][0] += w0*av;
                    sh[t][hf][1] += w1*av;
                    sh[t][hf][2] += w2*av;
                    sh[t][hf][3] += w3*av;
                }
        }
    }
    #pragma unroll
    for (int t=0;t<4;t++)
        #pragma unroll
        for (int hf=0;hf<2;hf++){
            float v4 = pl[t][hf];
            v4 += __shfl_xor_sync(0xffffffffu, v4, 1);
            v4 += __shfl_xor_sync(0xffffffffu, v4, 2);
            float vh[4];
            #pragma unroll
            for (int h=0;h<4;h++){
                float v = sh[t][hf][h];
                v += __shfl_xor_sync(0xffffffffu, v, 1);
                v += __shfl_xor_sync(0xffffffffu, v, 2);
                vh[h]=v;
            }
            if (j==0){
                int row = wm*64 + t*16 + qq + hf*8;
                float* rp = epi + EPI_RED + (row*4+wn)*5;
                rp[0]=vh[0]; rp[1]=vh[1]; rp[2]=vh[2]; rp[3]=vh[3]; rp[4]=v4;
            }
        }
    __syncthreads();

    // ---- phase B: per-row scores + sigmoid ----
    if (tid < 128){
        int row = tid;
        float s0=epi[EPI_DBS+0], s1=epi[EPI_DBS+1], s2=epi[EPI_DBS+2], s3=epi[EPI_DBS+3];
        float p=0.f;
        #pragma unroll
        for (int w=0;w<4;w++){
            float* rp = epi + EPI_RED + (row*4+w)*5;
            s0+=rp[0]; s1+=rp[1]; s2+=rp[2]; s3+=rp[3]; p+=rp[4];
        }
        epi[EPI_AW+row*4+0] = 1.f/(1.f+expf(-s0));
        epi[EPI_AW+row*4+1] = 1.f/(1.f+expf(-s1));
        epi[EPI_AW+row*4+2] = 1.f/(1.f+expf(-s2));
        epi[EPI_AW+row*4+3] = 1.f/(1.f+expf(-s3));
        epi[EPI_PL+row] = p;
    }
    __syncthreads();

    // ---- phase C: attention dot, 2 threads per row ----
    {
        int row = tid & 127, hf = tid >> 7;
        float a0=epi[EPI_AW+row*4+0], a1=epi[EPI_AW+row*4+1],
              a2=epi[EPI_AW+row*4+2], a3=epi[EPI_AW+row*4+3];
        float p2=0.f;
        #pragma unroll 8
        for (int d=hf*128; d<hf*128+128; d++){
            float att = epi[EPI_BASE+d] + a0*epi[EPI_CC+d] + a1*epi[EPI_CC+256+d]
                      + a2*epi[EPI_CC+512+d] + a3*epi[EPI_CC+768+d];
            p2 += fmaxf(att,0.f)*epi[EPI_WOA+d];
        }
        epi[EPI_RED2 + row*2 + hf] = p2;
    }
    __syncthreads();

    if (tid < 128){
        out[blockIdx.x*128 + tid] = epi[EPI_PL+tid] + epi[EPI_RED2+tid*2]
                                  + epi[EPI_RED2+tid*2+1] + __ldg(bo);
    }
}

// ---------------------------------------------------------------------------
extern "C" void kernel_launch(void* const* d_in, const int* in_sizes, int n_in,
                              void* d_out, int out_size){
    const float* user  = (const float*)d_in[0];
    const float* query = (const float*)d_in[1];
    const float* llm   = (const float*)d_in[2];
    const float* Wu    = (const float*)d_in[3];
    const float* bu    = (const float*)d_in[4];
    const float* Wq    = (const float*)d_in[5];
    const float* bq    = (const float*)d_in[6];
    const float* Wl    = (const float*)d_in[7];
    const float* bl    = (const float*)d_in[8];
    const float* ipw   = (const float*)d_in[9];
    const float* ipb   = (const float*)d_in[10];
    const float* opw   = (const float*)d_in[11];
    const float* opb   = (const float*)d_in[12];
    const float* Wo    = (const float*)d_in[13];
    const float* bo    = (const float*)d_in[14];
    float* out = (float*)d_out;

    int M = in_sizes[2] / 768;

    cudaFuncSetAttribute(main_gemm, cudaFuncAttributeMaxDynamicSharedMemorySize, SMEM_BYTES);

    prep_uq   <<<64, 256>>>(user, query, Wu, bu, Wq, bq);
    prep_kv   <<<128,256>>>(ipw, ipb);
    prep_small<<<417,256>>>(ipw, ipb, opw, opb);
    prep_const<<<1,  256>>>(bl);
    prep_Bh   <<<24, 256>>>(Wl);
    main_gemm <<<M/128, 256, SMEM_BYTES>>>(llm, Wo, bo, bl, out);
}